// round 2
// baseline (speedup 1.0000x reference)
#include <cuda_runtime.h>
#include <math.h>

// ---------------------------------------------------------------------------
// MLA prefill: B=2, S=2048, D=2048, H=16, DH=128
// Outputs (concatenated in d_out): out [B,S,D] fp32, then ckv [B,S,D] fp32
// ---------------------------------------------------------------------------

#define D_MODEL 2048
#define N_HEADS 16
#define DHEAD   128
#define SEQ     2048
#define BATCH   2
#define ROWS    (BATCH * SEQ)        // 4096
#define LN_EPS  1e-5f
#define QK_SCALE 0.08838834764831845f   // 1/sqrt(128)

// ------------------------- device scratch (no mallocs) ---------------------
__device__ float g_tmp[ROWS * D_MODEL];        // pre-LN scratch
__device__ float g_cq [ROWS * D_MODEL];
__device__ float g_q  [ROWS * D_MODEL];        // Q, [B,S,H,DH] flattened
__device__ float g_ckv[ROWS * D_MODEL];
__device__ float g_kv [ROWS * 2 * D_MODEL];    // K | V, [B,S, 2D]
__device__ float g_o  [ROWS * D_MODEL];        // attention out, [B,S,H,DH]

// ---------------------------------------------------------------------------
// SGEMM: C[M,N] = A[M,K] @ B[K,N]   (or A @ B^T when TRANSB, B stored [N,K])
// 128x128 block tile, BK=8, 8x8 per thread, 256 threads.
// ---------------------------------------------------------------------------
template <bool TRANSB>
__global__ void __launch_bounds__(256)
sgemm_kernel(const float* __restrict__ A, const float* __restrict__ B,
             float* __restrict__ C, int M, int N, int K)
{
    constexpr int BM = 128, BN = 128, BK = 8, TM = 8, TN = 8;
    __shared__ float As[BK][BM];
    __shared__ float Bs[BK][BN];

    const int tid  = threadIdx.x;
    const int bm   = blockIdx.y * BM;
    const int bn   = blockIdx.x * BN;
    const int trow = (tid >> 4) * TM;
    const int tcol = (tid & 15) * TN;

    const int aRow = tid >> 1;
    const int aCol = (tid & 1) << 2;
    const int bRow = tid >> 5;
    const int bCol = (tid & 31) << 2;

    float acc[TM][TN];
#pragma unroll
    for (int i = 0; i < TM; i++)
#pragma unroll
        for (int j = 0; j < TN; j++) acc[i][j] = 0.f;

    for (int k0 = 0; k0 < K; k0 += BK) {
        float4 av = *reinterpret_cast<const float4*>(&A[(size_t)(bm + aRow) * K + k0 + aCol]);
        As[aCol + 0][aRow] = av.x;
        As[aCol + 1][aRow] = av.y;
        As[aCol + 2][aRow] = av.z;
        As[aCol + 3][aRow] = av.w;

        if (TRANSB) {
            float4 bv = *reinterpret_cast<const float4*>(&B[(size_t)(bn + aRow) * K + k0 + aCol]);
            Bs[aCol + 0][aRow] = bv.x;
            Bs[aCol + 1][aRow] = bv.y;
            Bs[aCol + 2][aRow] = bv.z;
            Bs[aCol + 3][aRow] = bv.w;
        } else {
            float4 bv = *reinterpret_cast<const float4*>(&B[(size_t)(k0 + bRow) * N + bn + bCol]);
            *reinterpret_cast<float4*>(&Bs[bRow][bCol]) = bv;
        }
        __syncthreads();

#pragma unroll
        for (int k = 0; k < BK; k++) {
            float4 a0 = *reinterpret_cast<const float4*>(&As[k][trow]);
            float4 a1 = *reinterpret_cast<const float4*>(&As[k][trow + 4]);
            float4 b0 = *reinterpret_cast<const float4*>(&Bs[k][tcol]);
            float4 b1 = *reinterpret_cast<const float4*>(&Bs[k][tcol + 4]);
            float ar[TM] = {a0.x, a0.y, a0.z, a0.w, a1.x, a1.y, a1.z, a1.w};
            float br[TN] = {b0.x, b0.y, b0.z, b0.w, b1.x, b1.y, b1.z, b1.w};
#pragma unroll
            for (int i = 0; i < TM; i++)
#pragma unroll
                for (int j = 0; j < TN; j++) acc[i][j] += ar[i] * br[j];
        }
        __syncthreads();
    }

#pragma unroll
    for (int i = 0; i < TM; i++) {
        size_t crow = (size_t)(bm + trow + i) * N + bn + tcol;
        float4 w0 = make_float4(acc[i][0], acc[i][1], acc[i][2], acc[i][3]);
        float4 w1 = make_float4(acc[i][4], acc[i][5], acc[i][6], acc[i][7]);
        *reinterpret_cast<float4*>(&C[crow])     = w0;
        *reinterpret_cast<float4*>(&C[crow + 4]) = w1;
    }
}

// ---------------------------------------------------------------------------
// LayerNorm over rows of length D_MODEL; optionally mirrors to second output.
// ---------------------------------------------------------------------------
__global__ void __launch_bounds__(256)
ln_kernel(const float* __restrict__ in, const float* __restrict__ gamma,
          const float* __restrict__ beta, float* __restrict__ out0,
          float* __restrict__ out1)
{
    __shared__ float s_sum[8], s_sq[8];
    __shared__ float s_mu, s_rstd;
    const int row = blockIdx.x;
    const float* xr = in + (size_t)row * D_MODEL;

    float s = 0.f, sq = 0.f;
    for (int i = threadIdx.x * 4; i < D_MODEL; i += 256 * 4) {
        float4 v = *reinterpret_cast<const float4*>(&xr[i]);
        s  += v.x + v.y + v.z + v.w;
        sq += v.x * v.x + v.y * v.y + v.z * v.z + v.w * v.w;
    }
#pragma unroll
    for (int off = 16; off; off >>= 1) {
        s  += __shfl_down_sync(0xffffffffu, s, off);
        sq += __shfl_down_sync(0xffffffffu, sq, off);
    }
    if ((threadIdx.x & 31) == 0) { s_sum[threadIdx.x >> 5] = s; s_sq[threadIdx.x >> 5] = sq; }
    __syncthreads();
    if (threadIdx.x == 0) {
        float ts = 0.f, tq = 0.f;
#pragma unroll
        for (int w = 0; w < 8; w++) { ts += s_sum[w]; tq += s_sq[w]; }
        float mu  = ts * (1.f / D_MODEL);
        float var = tq * (1.f / D_MODEL) - mu * mu;
        s_mu = mu;
        s_rstd = rsqrtf(var + LN_EPS);
    }
    __syncthreads();
    const float mu = s_mu, rstd = s_rstd;
    for (int i = threadIdx.x * 4; i < D_MODEL; i += 256 * 4) {
        float4 v = *reinterpret_cast<const float4*>(&xr[i]);
        float4 g = *reinterpret_cast<const float4*>(&gamma[i]);
        float4 b = *reinterpret_cast<const float4*>(&beta[i]);
        float4 r;
        r.x = (v.x - mu) * rstd * g.x + b.x;
        r.y = (v.y - mu) * rstd * g.y + b.y;
        r.z = (v.z - mu) * rstd * g.z + b.z;
        r.w = (v.w - mu) * rstd * g.w + b.w;
        size_t o = (size_t)row * D_MODEL + i;
        *reinterpret_cast<float4*>(&out0[o]) = r;
        if (out1) *reinterpret_cast<float4*>(&out1[o]) = r;
    }
}

// ---------------------------------------------------------------------------
// RoPE in place on Q and K (first half of KV rows).
// ---------------------------------------------------------------------------
__global__ void rope_kernel(float* __restrict__ Q, float* __restrict__ KV)
{
    int idx = blockIdx.x * blockDim.x + threadIdx.x;
    if (idx >= ROWS * N_HEADS * 64) return;
    const int i   = idx & 63;
    const int h   = (idx >> 6) & (N_HEADS - 1);
    const int row = idx >> 10;
    const int t   = row & (SEQ - 1);

    const double freq = exp(-(double)i * (log(10000.0) / 64.0));
    double sd, cd;
    sincos((double)t * freq, &sd, &cd);
    const float c = (float)cd, s = (float)sd;

    size_t qb = (size_t)row * D_MODEL + h * DHEAD + i;
    float q1 = Q[qb], q2 = Q[qb + 64];
    Q[qb]      = q1 * c - q2 * s;
    Q[qb + 64] = q2 * c + q1 * s;

    size_t kb = (size_t)row * (2 * D_MODEL) + h * DHEAD + i;
    float k1 = KV[kb], k2 = KV[kb + 64];
    KV[kb]      = k1 * c - k2 * s;
    KV[kb + 64] = k2 * c + k1 * s;
}

// ---------------------------------------------------------------------------
// Flash attention (causal, fp32). 64x64 tiles, online softmax.
// ---------------------------------------------------------------------------
#define FA_BM 64
#define FA_BN 64
#define FA_DHP 132
#define FA_SN  65
#define FA_SMEM_FLOATS (FA_BM*FA_DHP + FA_BN*FA_DHP + FA_BM*FA_SN + 3*FA_BM)
#define FA_SMEM_BYTES  (FA_SMEM_FLOATS * 4)

__global__ void __launch_bounds__(256)
fa_kernel(const float* __restrict__ Q, const float* __restrict__ KV,
          float* __restrict__ O)
{
    extern __shared__ float sm[];
    float* Qs   = sm;
    float* KVs  = Qs  + FA_BM * FA_DHP;
    float* Ss   = KVs + FA_BN * FA_DHP;
    float* m_sh = Ss  + FA_BM * FA_SN;
    float* l_sh = m_sh + FA_BM;
    float* sc_sh = l_sh + FA_BM;

    const int tid  = threadIdx.x;
    const int trow = tid >> 4;
    const int tcol = tid & 15;
    const int b    = blockIdx.y >> 4;
    const int h    = blockIdx.y & (N_HEADS - 1);
    const int qi0  = blockIdx.x * FA_BM;

    const size_t qbase  = (size_t)(b * SEQ + qi0) * D_MODEL + h * DHEAD;
    const size_t kvbase = (size_t)(b * SEQ) * (2 * D_MODEL) + h * DHEAD;

    for (int idx = tid; idx < FA_BM * (DHEAD / 4); idx += 256) {
        int r = idx >> 5;
        int c = (idx & 31) << 2;
        float4 v = *reinterpret_cast<const float4*>(&Q[qbase + (size_t)r * D_MODEL + c]);
        v.x *= QK_SCALE; v.y *= QK_SCALE; v.z *= QK_SCALE; v.w *= QK_SCALE;
        *reinterpret_cast<float4*>(&Qs[r * FA_DHP + c]) = v;
    }
    if (tid < FA_BM) { m_sh[tid] = -INFINITY; l_sh[tid] = 0.f; }

    float oacc[4][8];
#pragma unroll
    for (int i = 0; i < 4; i++)
#pragma unroll
        for (int j = 0; j < 8; j++) oacc[i][j] = 0.f;

    const int ntiles = blockIdx.x + 1;
    for (int kt = 0; kt < ntiles; ++kt) {
        const int kj0 = kt * FA_BN;
        __syncthreads();
        for (int idx = tid; idx < FA_BN * (DHEAD / 4); idx += 256) {
            int r = idx >> 5;
            int c = (idx & 31) << 2;
            float4 v = *reinterpret_cast<const float4*>(
                &KV[kvbase + (size_t)(kj0 + r) * (2 * D_MODEL) + c]);
            *reinterpret_cast<float4*>(&KVs[r * FA_DHP + c]) = v;
        }
        __syncthreads();

        float sacc[4][4];
#pragma unroll
        for (int i = 0; i < 4; i++)
#pragma unroll
            for (int j = 0; j < 4; j++) sacc[i][j] = 0.f;

#pragma unroll 8
        for (int kk = 0; kk < DHEAD; kk += 4) {
            float4 qv[4], kv4[4];
#pragma unroll
            for (int i = 0; i < 4; i++)
                qv[i] = *reinterpret_cast<const float4*>(&Qs[(trow * 4 + i) * FA_DHP + kk]);
#pragma unroll
            for (int j = 0; j < 4; j++)
                kv4[j] = *reinterpret_cast<const float4*>(&KVs[(tcol * 4 + j) * FA_DHP + kk]);
#pragma unroll
            for (int i = 0; i < 4; i++)
#pragma unroll
                for (int j = 0; j < 4; j++)
                    sacc[i][j] += qv[i].x * kv4[j].x + qv[i].y * kv4[j].y +
                                  qv[i].z * kv4[j].z + qv[i].w * kv4[j].w;
        }

        const bool diag = (kt == blockIdx.x);
#pragma unroll
        for (int i = 0; i < 4; i++)
#pragma unroll
            for (int j = 0; j < 4; j++) {
                float sv = sacc[i][j];
                if (diag && (tcol * 4 + j > trow * 4 + i)) sv = -INFINITY;
                Ss[(trow * 4 + i) * FA_SN + tcol * 4 + j] = sv;
            }
        __syncthreads();

        if (tid < FA_BM) {
            float mprev = m_sh[tid];
            float mnew = mprev;
#pragma unroll 8
            for (int c = 0; c < FA_BN; c++) mnew = fmaxf(mnew, Ss[tid * FA_SN + c]);
            float sc = __expf(mprev - mnew);
            float lsum = 0.f;
#pragma unroll 8
            for (int c = 0; c < FA_BN; c++) {
                float p = __expf(Ss[tid * FA_SN + c] - mnew);
                Ss[tid * FA_SN + c] = p;
                lsum += p;
            }
            m_sh[tid] = mnew;
            l_sh[tid] = l_sh[tid] * sc + lsum;
            sc_sh[tid] = sc;
        }
        __syncthreads();

        float scr[4];
#pragma unroll
        for (int i = 0; i < 4; i++) scr[i] = sc_sh[trow * 4 + i];
#pragma unroll
        for (int i = 0; i < 4; i++)
#pragma unroll
            for (int j = 0; j < 8; j++) oacc[i][j] *= scr[i];

        for (int idx = tid; idx < FA_BN * (DHEAD / 4); idx += 256) {
            int r = idx >> 5;
            int c = (idx & 31) << 2;
            float4 v = *reinterpret_cast<const float4*>(
                &KV[kvbase + (size_t)(kj0 + r) * (2 * D_MODEL) + D_MODEL + c]);
            *reinterpret_cast<float4*>(&KVs[r * FA_DHP + c]) = v;
        }
        __syncthreads();

#pragma unroll 8
        for (int c = 0; c < FA_BN; c++) {
            float p0 = Ss[(trow * 4 + 0) * FA_SN + c];
            float p1 = Ss[(trow * 4 + 1) * FA_SN + c];
            float p2 = Ss[(trow * 4 + 2) * FA_SN + c];
            float p3 = Ss[(trow * 4 + 3) * FA_SN + c];
            float4 v0 = *reinterpret_cast<const float4*>(&KVs[c * FA_DHP + tcol * 8]);
            float4 v1 = *reinterpret_cast<const float4*>(&KVs[c * FA_DHP + tcol * 8 + 4]);
            oacc[0][0] += p0 * v0.x; oacc[0][1] += p0 * v0.y; oacc[0][2] += p0 * v0.z; oacc[0][3] += p0 * v0.w;
            oacc[0][4] += p0 * v1.x; oacc[0][5] += p0 * v1.y; oacc[0][6] += p0 * v1.z; oacc[0][7] += p0 * v1.w;
            oacc[1][0] += p1 * v0.x; oacc[1][1] += p1 * v0.y; oacc[1][2] += p1 * v0.z; oacc[1][3] += p1 * v0.w;
            oacc[1][4] += p1 * v1.x; oacc[1][5] += p1 * v1.y; oacc[1][6] += p1 * v1.z; oacc[1][7] += p1 * v1.w;
            oacc[2][0] += p2 * v0.x; oacc[2][1] += p2 * v0.y; oacc[2][2] += p2 * v0.z; oacc[2][3] += p2 * v0.w;
            oacc[2][4] += p2 * v1.x; oacc[2][5] += p2 * v1.y; oacc[2][6] += p2 * v1.z; oacc[2][7] += p2 * v1.w;
            oacc[3][0] += p3 * v0.x; oacc[3][1] += p3 * v0.y; oacc[3][2] += p3 * v0.z; oacc[3][3] += p3 * v0.w;
            oacc[3][4] += p3 * v1.x; oacc[3][5] += p3 * v1.y; oacc[3][6] += p3 * v1.z; oacc[3][7] += p3 * v1.w;
        }
    }

#pragma unroll
    for (int i = 0; i < 4; i++) {
        float inv = 1.f / l_sh[trow * 4 + i];
        float4 w0 = make_float4(oacc[i][0] * inv, oacc[i][1] * inv, oacc[i][2] * inv, oacc[i][3] * inv);
        float4 w1 = make_float4(oacc[i][4] * inv, oacc[i][5] * inv, oacc[i][6] * inv, oacc[i][7] * inv);
        size_t ob = (size_t)(b * SEQ + qi0 + trow * 4 + i) * D_MODEL + h * DHEAD + tcol * 8;
        *reinterpret_cast<float4*>(&O[ob])     = w0;
        *reinterpret_cast<float4*>(&O[ob + 4]) = w1;
    }
}

// ---------------------------------------------------------------------------
extern "C" void kernel_launch(void* const* d_in, const int* in_sizes, int n_in,
                              void* d_out, int out_size)
{
    (void)in_sizes; (void)n_in;
    const float* x        = (const float*)d_in[0];
    const float* W_dq     = (const float*)d_in[1];
    const float* W_uq     = (const float*)d_in[2];
    const float* q_gamma  = (const float*)d_in[3];
    const float* q_beta   = (const float*)d_in[4];
    const float* W_dkv    = (const float*)d_in[5];
    const float* W_ukv    = (const float*)d_in[6];
    const float* kv_gamma = (const float*)d_in[7];
    const float* kv_beta  = (const float*)d_in[8];
    const float* W_o      = (const float*)d_in[9];

    float* out     = (float*)d_out;
    float* ckv_out = out + (size_t)out_size / 2;

    float *tmp, *cq, *q, *ckv, *kv, *o;
    cudaGetSymbolAddress((void**)&tmp, g_tmp);
    cudaGetSymbolAddress((void**)&cq,  g_cq);
    cudaGetSymbolAddress((void**)&q,   g_q);
    cudaGetSymbolAddress((void**)&ckv, g_ckv);
    cudaGetSymbolAddress((void**)&kv,  g_kv);
    cudaGetSymbolAddress((void**)&o,   g_o);

    const dim3 gD(D_MODEL / 128, ROWS / 128);
    const dim3 g2D(2 * D_MODEL / 128, ROWS / 128);

    sgemm_kernel<false><<<gD, 256>>>(x, W_dq, tmp, ROWS, D_MODEL, D_MODEL);
    ln_kernel<<<ROWS, 256>>>(tmp, q_gamma, q_beta, cq, nullptr);
    sgemm_kernel<false><<<gD, 256>>>(cq, W_uq, q, ROWS, D_MODEL, D_MODEL);

    sgemm_kernel<false><<<gD, 256>>>(x, W_dkv, tmp, ROWS, D_MODEL, D_MODEL);
    ln_kernel<<<ROWS, 256>>>(tmp, kv_gamma, kv_beta, ckv, ckv_out);
    sgemm_kernel<false><<<g2D, 256>>>(ckv, W_ukv, kv, ROWS, 2 * D_MODEL, D_MODEL);

    int nrope = ROWS * N_HEADS * 64;
    rope_kernel<<<(nrope + 255) / 256, 256>>>(q, kv);

    cudaFuncSetAttribute(fa_kernel, cudaFuncAttributeMaxDynamicSharedMemorySize,
                         FA_SMEM_BYTES);
    fa_kernel<<<dim3(SEQ / FA_BM, BATCH * N_HEADS), 256, FA_SMEM_BYTES>>>(q, kv, o);

    sgemm_kernel<true><<<gD, 256>>>(o, W_o, out, ROWS, D_MODEL, D_MODEL);
}

// round 3
// speedup vs baseline: 1.1056x; 1.1056x over previous
#include <cuda_runtime.h>
#include <math.h>
#include <stdint.h>

// ---------------------------------------------------------------------------
// MLA prefill: B=2, S=2048, D=2048, H=16, DH=128
// Outputs (concatenated in d_out): out [B,S,D] fp32, then ckv [B,S,D] fp32
// ---------------------------------------------------------------------------

#define D_MODEL 2048
#define N_HEADS 16
#define DHEAD   128
#define SEQ     2048
#define BATCH   2
#define ROWS    (BATCH * SEQ)        // 4096
#define LN_EPS  1e-5f
#define QK_SCALE 0.08838834764831845f   // 1/sqrt(128)

// ------------------------- device scratch (no mallocs) ---------------------
__device__ float g_tmp[ROWS * D_MODEL];        // pre-LN scratch
__device__ float g_cq [ROWS * D_MODEL];
__device__ float g_q  [ROWS * D_MODEL];        // Q, [B,S,H,DH] flattened
__device__ float g_ckv[ROWS * D_MODEL];
__device__ float g_kv [ROWS * 2 * D_MODEL];    // K | V, [B,S, 2D]
__device__ float g_o  [ROWS * D_MODEL];        // attention out, [B,S,H,DH]

// ---------------------------------------------------------------------------
// tf32 helpers
// ---------------------------------------------------------------------------
__device__ __forceinline__ uint32_t f2tf32(float x) {
    uint32_t r;
    asm("cvt.rna.tf32.f32 %0, %1;" : "=r"(r) : "f"(x));
    return r;
}

__device__ __forceinline__ void mma_tf32(float* d, const uint32_t* a, const uint32_t* b) {
    asm volatile(
        "mma.sync.aligned.m16n8k8.row.col.f32.tf32.tf32.f32 "
        "{%0,%1,%2,%3}, {%4,%5,%6,%7}, {%8,%9}, {%0,%1,%2,%3};"
        : "+f"(d[0]), "+f"(d[1]), "+f"(d[2]), "+f"(d[3])
        : "r"(a[0]), "r"(a[1]), "r"(a[2]), "r"(a[3]), "r"(b[0]), "r"(b[1]));
}

// k-permutation within groups of 8: element k goes to column (k&~7) | p,
// p = 2*(k%4) + (k/4 % 2). A thread's two k-elements {ti, ti+4} land adjacent.
__device__ __forceinline__ int kperm(int k) {
    int kin = k & 7;
    return (k & ~7) | (((kin & 3) << 1) | (kin >> 2));
}

// ---------------------------------------------------------------------------
// tf32 tensor-core GEMM: C[M,N] = A[M,K] @ B[K,N]  (TRANSB: B stored [N,K])
// 128x128 block, BK=32, 256 threads = 8 warps (2x4), warp tile 64x32.
// Smem: k-interleaved, row stride 40 floats (conflict-free fragment reads).
// ---------------------------------------------------------------------------
template <bool TRANSB>
__global__ void __launch_bounds__(256)
tgemm_kernel(const float* __restrict__ A, const float* __restrict__ B,
             float* __restrict__ C, int M, int N, int K)
{
    constexpr int BK = 32;
    constexpr int LDS_S = 40;
    __shared__ uint32_t As[128 * LDS_S];
    __shared__ uint32_t Bs[128 * LDS_S];

    const int tid  = threadIdx.x;
    const int lane = tid & 31;
    const int wid  = tid >> 5;
    const int g    = lane >> 2;   // 0..7
    const int ti   = lane & 3;    // 0..3
    const int wm   = (wid >> 2) * 64;   // warp row offset (0 or 64)
    const int wn   = (wid & 3) * 32;    // warp col offset (0..96)

    const int bm = blockIdx.y * 128;
    const int bn = blockIdx.x * 128;

    // --- gmem load mappings (per chunk of 256 float4s) ---
    // A: 128 rows x 8 float4 of k
    const int aRow = tid >> 3;          // within chunk: row = chunk*32 + aRow? no:
    // idx = chunk*256 + tid; row = idx>>3 -> row advances by 32 per chunk
    const int aC4  = (tid & 7) << 2;

    float4 pa[4], pb[4];

    // load A/B tile for k0 into registers
    auto load_tiles = [&](int k0) {
#pragma unroll
        for (int ch = 0; ch < 4; ch++) {
            int row = ch * 32 + aRow;
            pa[ch] = *reinterpret_cast<const float4*>(
                &A[(size_t)(bm + row) * K + k0 + aC4]);
        }
        if (TRANSB) {
#pragma unroll
            for (int ch = 0; ch < 4; ch++) {
                int row = ch * 32 + aRow;
                pb[ch] = *reinterpret_cast<const float4*>(
                    &B[(size_t)(bn + row) * K + k0 + aC4]);
            }
        } else {
            // B[K][N]: 32 k-rows x 32 float4 of n per chunk? total 32x128 floats
            // idx = ch*256 + tid; kr = idx>>5 (0..31), c4 = (idx&31)<<2
#pragma unroll
            for (int ch = 0; ch < 4; ch++) {
                int idx = ch * 256 + tid;
                int kr  = idx >> 5;
                int c4  = (idx & 31) << 2;
                pb[ch] = *reinterpret_cast<const float4*>(
                    &B[(size_t)(k0 + kr) * N + bn + c4]);
            }
        }
    };

    auto store_tiles = [&]() {
#pragma unroll
        for (int ch = 0; ch < 4; ch++) {
            int row = ch * 32 + aRow;
            const float* v = reinterpret_cast<const float*>(&pa[ch]);
#pragma unroll
            for (int j = 0; j < 4; j++)
                As[row * LDS_S + kperm(aC4 + j)] = f2tf32(v[j]);
        }
        if (TRANSB) {
#pragma unroll
            for (int ch = 0; ch < 4; ch++) {
                int row = ch * 32 + aRow;
                const float* v = reinterpret_cast<const float*>(&pb[ch]);
#pragma unroll
                for (int j = 0; j < 4; j++)
                    Bs[row * LDS_S + kperm(aC4 + j)] = f2tf32(v[j]);
            }
        } else {
#pragma unroll
            for (int ch = 0; ch < 4; ch++) {
                int idx = ch * 256 + tid;
                int kr  = idx >> 5;
                int c4  = (idx & 31) << 2;
                int kc  = kperm(kr);
                const float* v = reinterpret_cast<const float*>(&pb[ch]);
#pragma unroll
                for (int j = 0; j < 4; j++)
                    Bs[(c4 + j) * LDS_S + kc] = f2tf32(v[j]);
            }
        }
    };

    float acc[4][4][4];
#pragma unroll
    for (int mt = 0; mt < 4; mt++)
#pragma unroll
        for (int nt = 0; nt < 4; nt++)
#pragma unroll
            for (int r = 0; r < 4; r++) acc[mt][nt][r] = 0.f;

    const int niter = K / BK;
    load_tiles(0);
    store_tiles();
    __syncthreads();

    for (int it = 0; it < niter; it++) {
        if (it + 1 < niter) load_tiles((it + 1) * BK);

#pragma unroll
        for (int ks = 0; ks < 4; ks++) {
            const int kb = ks * 8;
            uint32_t af[4][4];
#pragma unroll
            for (int mt = 0; mt < 4; mt++) {
                int r = wm + mt * 16 + g;
                uint2 lo = *reinterpret_cast<const uint2*>(&As[r * LDS_S + kb + 2 * ti]);
                uint2 hi = *reinterpret_cast<const uint2*>(&As[(r + 8) * LDS_S + kb + 2 * ti]);
                af[mt][0] = lo.x; af[mt][2] = lo.y;
                af[mt][1] = hi.x; af[mt][3] = hi.y;
            }
            uint32_t bf[4][2];
#pragma unroll
            for (int nt = 0; nt < 4; nt++) {
                uint2 bb = *reinterpret_cast<const uint2*>(
                    &Bs[(wn + nt * 8 + g) * LDS_S + kb + 2 * ti]);
                bf[nt][0] = bb.x; bf[nt][1] = bb.y;
            }
#pragma unroll
            for (int mt = 0; mt < 4; mt++)
#pragma unroll
                for (int nt = 0; nt < 4; nt++)
                    mma_tf32(acc[mt][nt], af[mt], bf[nt]);
        }

        if (it + 1 < niter) {
            __syncthreads();
            store_tiles();
            __syncthreads();
        }
    }

    // epilogue
#pragma unroll
    for (int mt = 0; mt < 4; mt++) {
#pragma unroll
        for (int nt = 0; nt < 4; nt++) {
            int r0 = bm + wm + mt * 16 + g;
            int c0 = bn + wn + nt * 8 + 2 * ti;
            float2 w0 = make_float2(acc[mt][nt][0], acc[mt][nt][1]);
            float2 w1 = make_float2(acc[mt][nt][2], acc[mt][nt][3]);
            *reinterpret_cast<float2*>(&C[(size_t)r0 * N + c0]) = w0;
            *reinterpret_cast<float2*>(&C[(size_t)(r0 + 8) * N + c0]) = w1;
        }
    }
}

// ---------------------------------------------------------------------------
// LayerNorm over rows of length D_MODEL; optionally mirrors to second output.
// ---------------------------------------------------------------------------
__global__ void __launch_bounds__(256)
ln_kernel(const float* __restrict__ in, const float* __restrict__ gamma,
          const float* __restrict__ beta, float* __restrict__ out0,
          float* __restrict__ out1)
{
    __shared__ float s_sum[8], s_sq[8];
    __shared__ float s_mu, s_rstd;
    const int row = blockIdx.x;
    const float* xr = in + (size_t)row * D_MODEL;

    float s = 0.f, sq = 0.f;
    for (int i = threadIdx.x * 4; i < D_MODEL; i += 256 * 4) {
        float4 v = *reinterpret_cast<const float4*>(&xr[i]);
        s  += v.x + v.y + v.z + v.w;
        sq += v.x * v.x + v.y * v.y + v.z * v.z + v.w * v.w;
    }
#pragma unroll
    for (int off = 16; off; off >>= 1) {
        s  += __shfl_down_sync(0xffffffffu, s, off);
        sq += __shfl_down_sync(0xffffffffu, sq, off);
    }
    if ((threadIdx.x & 31) == 0) { s_sum[threadIdx.x >> 5] = s; s_sq[threadIdx.x >> 5] = sq; }
    __syncthreads();
    if (threadIdx.x == 0) {
        float ts = 0.f, tq = 0.f;
#pragma unroll
        for (int w = 0; w < 8; w++) { ts += s_sum[w]; tq += s_sq[w]; }
        float mu  = ts * (1.f / D_MODEL);
        float var = tq * (1.f / D_MODEL) - mu * mu;
        s_mu = mu;
        s_rstd = rsqrtf(var + LN_EPS);
    }
    __syncthreads();
    const float mu = s_mu, rstd = s_rstd;
    for (int i = threadIdx.x * 4; i < D_MODEL; i += 256 * 4) {
        float4 v = *reinterpret_cast<const float4*>(&xr[i]);
        float4 g = *reinterpret_cast<const float4*>(&gamma[i]);
        float4 b = *reinterpret_cast<const float4*>(&beta[i]);
        float4 r;
        r.x = (v.x - mu) * rstd * g.x + b.x;
        r.y = (v.y - mu) * rstd * g.y + b.y;
        r.z = (v.z - mu) * rstd * g.z + b.z;
        r.w = (v.w - mu) * rstd * g.w + b.w;
        size_t o = (size_t)row * D_MODEL + i;
        *reinterpret_cast<float4*>(&out0[o]) = r;
        if (out1) *reinterpret_cast<float4*>(&out1[o]) = r;
    }
}

// ---------------------------------------------------------------------------
// RoPE in place on Q and K (first half of KV rows).
// ---------------------------------------------------------------------------
__global__ void rope_kernel(float* __restrict__ Q, float* __restrict__ KV)
{
    int idx = blockIdx.x * blockDim.x + threadIdx.x;
    if (idx >= ROWS * N_HEADS * 64) return;
    const int i   = idx & 63;
    const int h   = (idx >> 6) & (N_HEADS - 1);
    const int row = idx >> 10;
    const int t   = row & (SEQ - 1);

    const double freq = exp(-(double)i * (log(10000.0) / 64.0));
    double sd, cd;
    sincos((double)t * freq, &sd, &cd);
    const float c = (float)cd, s = (float)sd;

    size_t qb = (size_t)row * D_MODEL + h * DHEAD + i;
    float q1 = Q[qb], q2 = Q[qb + 64];
    Q[qb]      = q1 * c - q2 * s;
    Q[qb + 64] = q2 * c + q1 * s;

    size_t kb = (size_t)row * (2 * D_MODEL) + h * DHEAD + i;
    float k1 = KV[kb], k2 = KV[kb + 64];
    KV[kb]      = k1 * c - k2 * s;
    KV[kb + 64] = k2 * c + k1 * s;
}

// ---------------------------------------------------------------------------
// Flash attention (causal, fp32). 64x64 tiles, online softmax.
// ---------------------------------------------------------------------------
#define FA_BM 64
#define FA_BN 64
#define FA_DHP 132
#define FA_SN  65
#define FA_SMEM_FLOATS (FA_BM*FA_DHP + FA_BN*FA_DHP + FA_BM*FA_SN + 3*FA_BM)
#define FA_SMEM_BYTES  (FA_SMEM_FLOATS * 4)

__global__ void __launch_bounds__(256)
fa_kernel(const float* __restrict__ Q, const float* __restrict__ KV,
          float* __restrict__ O)
{
    extern __shared__ float sm[];
    float* Qs   = sm;
    float* KVs  = Qs  + FA_BM * FA_DHP;
    float* Ss   = KVs + FA_BN * FA_DHP;
    float* m_sh = Ss  + FA_BM * FA_SN;
    float* l_sh = m_sh + FA_BM;
    float* sc_sh = l_sh + FA_BM;

    const int tid  = threadIdx.x;
    const int trow = tid >> 4;
    const int tcol = tid & 15;
    const int b    = blockIdx.y >> 4;
    const int h    = blockIdx.y & (N_HEADS - 1);
    const int qi0  = blockIdx.x * FA_BM;

    const size_t qbase  = (size_t)(b * SEQ + qi0) * D_MODEL + h * DHEAD;
    const size_t kvbase = (size_t)(b * SEQ) * (2 * D_MODEL) + h * DHEAD;

    for (int idx = tid; idx < FA_BM * (DHEAD / 4); idx += 256) {
        int r = idx >> 5;
        int c = (idx & 31) << 2;
        float4 v = *reinterpret_cast<const float4*>(&Q[qbase + (size_t)r * D_MODEL + c]);
        v.x *= QK_SCALE; v.y *= QK_SCALE; v.z *= QK_SCALE; v.w *= QK_SCALE;
        *reinterpret_cast<float4*>(&Qs[r * FA_DHP + c]) = v;
    }
    if (tid < FA_BM) { m_sh[tid] = -INFINITY; l_sh[tid] = 0.f; }

    float oacc[4][8];
#pragma unroll
    for (int i = 0; i < 4; i++)
#pragma unroll
        for (int j = 0; j < 8; j++) oacc[i][j] = 0.f;

    const int ntiles = blockIdx.x + 1;
    for (int kt = 0; kt < ntiles; ++kt) {
        const int kj0 = kt * FA_BN;
        __syncthreads();
        for (int idx = tid; idx < FA_BN * (DHEAD / 4); idx += 256) {
            int r = idx >> 5;
            int c = (idx & 31) << 2;
            float4 v = *reinterpret_cast<const float4*>(
                &KV[kvbase + (size_t)(kj0 + r) * (2 * D_MODEL) + c]);
            *reinterpret_cast<float4*>(&KVs[r * FA_DHP + c]) = v;
        }
        __syncthreads();

        float sacc[4][4];
#pragma unroll
        for (int i = 0; i < 4; i++)
#pragma unroll
            for (int j = 0; j < 4; j++) sacc[i][j] = 0.f;

#pragma unroll 8
        for (int kk = 0; kk < DHEAD; kk += 4) {
            float4 qv[4], kv4[4];
#pragma unroll
            for (int i = 0; i < 4; i++)
                qv[i] = *reinterpret_cast<const float4*>(&Qs[(trow * 4 + i) * FA_DHP + kk]);
#pragma unroll
            for (int j = 0; j < 4; j++)
                kv4[j] = *reinterpret_cast<const float4*>(&KVs[(tcol * 4 + j) * FA_DHP + kk]);
#pragma unroll
            for (int i = 0; i < 4; i++)
#pragma unroll
                for (int j = 0; j < 4; j++)
                    sacc[i][j] += qv[i].x * kv4[j].x + qv[i].y * kv4[j].y +
                                  qv[i].z * kv4[j].z + qv[i].w * kv4[j].w;
        }

        const bool diag = (kt == blockIdx.x);
#pragma unroll
        for (int i = 0; i < 4; i++)
#pragma unroll
            for (int j = 0; j < 4; j++) {
                float sv = sacc[i][j];
                if (diag && (tcol * 4 + j > trow * 4 + i)) sv = -INFINITY;
                Ss[(trow * 4 + i) * FA_SN + tcol * 4 + j] = sv;
            }
        __syncthreads();

        if (tid < FA_BM) {
            float mprev = m_sh[tid];
            float mnew = mprev;
#pragma unroll 8
            for (int c = 0; c < FA_BN; c++) mnew = fmaxf(mnew, Ss[tid * FA_SN + c]);
            float sc = __expf(mprev - mnew);
            float lsum = 0.f;
#pragma unroll 8
            for (int c = 0; c < FA_BN; c++) {
                float p = __expf(Ss[tid * FA_SN + c] - mnew);
                Ss[tid * FA_SN + c] = p;
                lsum += p;
            }
            m_sh[tid] = mnew;
            l_sh[tid] = l_sh[tid] * sc + lsum;
            sc_sh[tid] = sc;
        }
        __syncthreads();

        float scr[4];
#pragma unroll
        for (int i = 0; i < 4; i++) scr[i] = sc_sh[trow * 4 + i];
#pragma unroll
        for (int i = 0; i < 4; i++)
#pragma unroll
            for (int j = 0; j < 8; j++) oacc[i][j] *= scr[i];

        for (int idx = tid; idx < FA_BN * (DHEAD / 4); idx += 256) {
            int r = idx >> 5;
            int c = (idx & 31) << 2;
            float4 v = *reinterpret_cast<const float4*>(
                &KV[kvbase + (size_t)(kj0 + r) * (2 * D_MODEL) + D_MODEL + c]);
            *reinterpret_cast<float4*>(&KVs[r * FA_DHP + c]) = v;
        }
        __syncthreads();

#pragma unroll 8
        for (int c = 0; c < FA_BN; c++) {
            float p0 = Ss[(trow * 4 + 0) * FA_SN + c];
            float p1 = Ss[(trow * 4 + 1) * FA_SN + c];
            float p2 = Ss[(trow * 4 + 2) * FA_SN + c];
            float p3 = Ss[(trow * 4 + 3) * FA_SN + c];
            float4 v0 = *reinterpret_cast<const float4*>(&KVs[c * FA_DHP + tcol * 8]);
            float4 v1 = *reinterpret_cast<const float4*>(&KVs[c * FA_DHP + tcol * 8 + 4]);
            oacc[0][0] += p0 * v0.x; oacc[0][1] += p0 * v0.y; oacc[0][2] += p0 * v0.z; oacc[0][3] += p0 * v0.w;
            oacc[0][4] += p0 * v1.x; oacc[0][5] += p0 * v1.y; oacc[0][6] += p0 * v1.z; oacc[0][7] += p0 * v1.w;
            oacc[1][0] += p1 * v0.x; oacc[1][1] += p1 * v0.y; oacc[1][2] += p1 * v0.z; oacc[1][3] += p1 * v0.w;
            oacc[1][4] += p1 * v1.x; oacc[1][5] += p1 * v1.y; oacc[1][6] += p1 * v1.z; oacc[1][7] += p1 * v1.w;
            oacc[2][0] += p2 * v0.x; oacc[2][1] += p2 * v0.y; oacc[2][2] += p2 * v0.z; oacc[2][3] += p2 * v0.w;
            oacc[2][4] += p2 * v1.x; oacc[2][5] += p2 * v1.y; oacc[2][6] += p2 * v1.z; oacc[2][7] += p2 * v1.w;
            oacc[3][0] += p3 * v0.x; oacc[3][1] += p3 * v0.y; oacc[3][2] += p3 * v0.z; oacc[3][3] += p3 * v0.w;
            oacc[3][4] += p3 * v1.x; oacc[3][5] += p3 * v1.y; oacc[3][6] += p3 * v1.z; oacc[3][7] += p3 * v1.w;
        }
    }

#pragma unroll
    for (int i = 0; i < 4; i++) {
        float inv = 1.f / l_sh[trow * 4 + i];
        float4 w0 = make_float4(oacc[i][0] * inv, oacc[i][1] * inv, oacc[i][2] * inv, oacc[i][3] * inv);
        float4 w1 = make_float4(oacc[i][4] * inv, oacc[i][5] * inv, oacc[i][6] * inv, oacc[i][7] * inv);
        size_t ob = (size_t)(b * SEQ + qi0 + trow * 4 + i) * D_MODEL + h * DHEAD + tcol * 8;
        *reinterpret_cast<float4*>(&O[ob])     = w0;
        *reinterpret_cast<float4*>(&O[ob + 4]) = w1;
    }
}

// ---------------------------------------------------------------------------
extern "C" void kernel_launch(void* const* d_in, const int* in_sizes, int n_in,
                              void* d_out, int out_size)
{
    (void)in_sizes; (void)n_in;
    const float* x        = (const float*)d_in[0];
    const float* W_dq     = (const float*)d_in[1];
    const float* W_uq     = (const float*)d_in[2];
    const float* q_gamma  = (const float*)d_in[3];
    const float* q_beta   = (const float*)d_in[4];
    const float* W_dkv    = (const float*)d_in[5];
    const float* W_ukv    = (const float*)d_in[6];
    const float* kv_gamma = (const float*)d_in[7];
    const float* kv_beta  = (const float*)d_in[8];
    const float* W_o      = (const float*)d_in[9];

    float* out     = (float*)d_out;
    float* ckv_out = out + (size_t)out_size / 2;

    float *tmp, *cq, *q, *ckv, *kv, *o;
    cudaGetSymbolAddress((void**)&tmp, g_tmp);
    cudaGetSymbolAddress((void**)&cq,  g_cq);
    cudaGetSymbolAddress((void**)&q,   g_q);
    cudaGetSymbolAddress((void**)&ckv, g_ckv);
    cudaGetSymbolAddress((void**)&kv,  g_kv);
    cudaGetSymbolAddress((void**)&o,   g_o);

    const dim3 gD(D_MODEL / 128, ROWS / 128);       // (16, 32)
    const dim3 g2D(2 * D_MODEL / 128, ROWS / 128);  // (32, 32)

    // Q path
    tgemm_kernel<false><<<gD, 256>>>(x, W_dq, tmp, ROWS, D_MODEL, D_MODEL);
    ln_kernel<<<ROWS, 256>>>(tmp, q_gamma, q_beta, cq, nullptr);
    tgemm_kernel<false><<<gD, 256>>>(cq, W_uq, q, ROWS, D_MODEL, D_MODEL);

    // KV path (ckv is also output #2)
    tgemm_kernel<false><<<gD, 256>>>(x, W_dkv, tmp, ROWS, D_MODEL, D_MODEL);
    ln_kernel<<<ROWS, 256>>>(tmp, kv_gamma, kv_beta, ckv, ckv_out);
    tgemm_kernel<false><<<g2D, 256>>>(ckv, W_ukv, kv, ROWS, 2 * D_MODEL, D_MODEL);

    // RoPE on Q and K (in place)
    int nrope = ROWS * N_HEADS * 64;
    rope_kernel<<<(nrope + 255) / 256, 256>>>(q, kv);

    // Causal flash attention
    cudaFuncSetAttribute(fa_kernel, cudaFuncAttributeMaxDynamicSharedMemorySize,
                         FA_SMEM_BYTES);
    fa_kernel<<<dim3(SEQ / FA_BM, BATCH * N_HEADS), 256, FA_SMEM_BYTES>>>(q, kv, o);

    // out = o @ W_o^T
    tgemm_kernel<true><<<gD, 256>>>(o, W_o, out, ROWS, D_MODEL, D_MODEL);
}